// round 5
// baseline (speedup 1.0000x reference)
#include <cuda_runtime.h>
#include <math.h>

static constexpr int T    = 32;
static constexpr int IMGW = 512, IMGH = 512, NIMG = 48;   // 16*3 images of 512x512
static constexpr int TILES = (IMGW / T) * (IMGH / T) * NIMG;  // 12288
static constexpr float FEPS = 1e-8f;

// per-(window,block) partial sums; every slot written every launch -> deterministic
__device__ double g_partial[3 * TILES];

template <int K>
__global__ __launch_bounds__(256)
void statloss_kernel(const float* __restrict__ pred,
                     const float* __restrict__ target,
                     int winIdx)
{
    constexpr int R  = K / 2;
    constexpr int H  = T + 4 * R;          // x tile extent (halo 2R)
    constexpr int M  = T + 2 * R;          // mean/xc extent (halo R)
    constexpr int XS = ((H + 3) / 4) * 4;  // float4-aligned strides
    constexpr int MS = ((M + 3) / 4) * 4;
    constexpr int NV = (2 * R + 7) / 4;    // float4 loads per horizontal output-quad
    constexpr int NG = (M + 3) / 4;        // col groups (P1) / row groups (P2)
    constexpr int P1_ITEMS = H * NG;
    constexpr int P2_ITEMS = NG * M;
    constexpr int P4_ITEMS = M * 8;

    __shared__ __align__(16) float sX[H * XS];
    __shared__ __align__(16) float sT1[H * MS];
    __shared__ __align__(16) float sT2[H * MS];
    __shared__ __align__(16) float sMEAN[M * MS];
    __shared__ __align__(16) float sC3[M * MS];
    __shared__ __align__(16) float sC4[M * MS];
    __shared__ double sRed[8];

    const int tid = threadIdx.x;
    const int tx  = tid & 31;
    const int ty  = tid >> 5;   // 0..7 -> owns center rows 4*ty .. 4*ty+3

    // normalized 1-D gaussian (separable; outer product is already sum-1)
    float g[K];
    {
        const float sigma = (float)K / 6.0f;
        float s = 0.f;
#pragma unroll
        for (int i = 0; i < K; i++) {
            float c = (float)(i - K / 2);
            g[i] = expf(-c * c / (2.0f * sigma * sigma));
            s += g[i];
        }
#pragma unroll
        for (int i = 0; i < K; i++) g[i] /= s;
    }

    const int gx0 = blockIdx.x * T;
    const int gy0 = blockIdx.y * T;
    const size_t base = (size_t)blockIdx.z * IMGH * IMGW;

    float fpm[4], fpv[4], fps[4], fpk[4];   // pred features (which==0)
    double acc = 0.0;

    for (int which = 0; which < 2; which++) {
        const float* xin = (which == 0 ? pred : target) + base;

        // ---- load x tile with 2R halo (zero pad outside image) ----
        for (int idx = tid; idx < H * H; idx += 256) {
            int j = idx / H, i = idx - j * H;
            int gy = gy0 - 2 * R + j, gx = gx0 - 2 * R + i;
            float v = 0.f;
            if ((unsigned)gy < (unsigned)IMGH && (unsigned)gx < (unsigned)IMGW)
                v = xin[(size_t)gy * IMGW + gx];
            sX[j * XS + i] = v;
        }
        __syncthreads();

        // ---- P1: horizontal conv of x and x^2 (H rows x M cols), 4 cols/thread ----
#pragma unroll
        for (int it = 0; it < (P1_ITEMS + 255) / 256; it++) {
            int item = tid + it * 256;
            if (item < P1_ITEMS) {
                int j = item / NG, g4 = item - j * NG;
                float x[4 * NV], x2[4 * NV];
                const float4* src = reinterpret_cast<const float4*>(&sX[j * XS + 4 * g4]);
#pragma unroll
                for (int w = 0; w < NV; w++) {
                    float4 v = src[w];
                    x[4 * w + 0] = v.x; x[4 * w + 1] = v.y;
                    x[4 * w + 2] = v.z; x[4 * w + 3] = v.w;
                }
#pragma unroll
                for (int i = 0; i < 4 * NV; i++) x2[i] = x[i] * x[i];
                float a[4] = {0.f, 0.f, 0.f, 0.f};
                float b[4] = {0.f, 0.f, 0.f, 0.f};
#pragma unroll
                for (int d = 0; d < K; d++)
#pragma unroll
                    for (int q = 0; q < 4; q++) {
                        a[q] = fmaf(g[d], x[q + d],  a[q]);
                        b[q] = fmaf(g[d], x2[q + d], b[q]);
                    }
                *reinterpret_cast<float4*>(&sT1[j * MS + 4 * g4]) =
                    make_float4(a[0], a[1], a[2], a[3]);
                *reinterpret_cast<float4*>(&sT2[j * MS + 4 * g4]) =
                    make_float4(b[0], b[1], b[2], b[3]);
            }
        }
        __syncthreads();

        // ---- P2: vertical conv -> MEAN (M x M), 4 rows/thread ----
#pragma unroll
        for (int it = 0; it < (P2_ITEMS + 255) / 256; it++) {
            int item = tid + it * 256;
            if (item < P2_ITEMS) {
                int rg = item / M, c = item - rg * M;
                float r[K + 3];
#pragma unroll
                for (int d = 0; d < K + 3; d++)
                    r[d] = sT1[(4 * rg + d) * MS + c];
#pragma unroll
                for (int q = 0; q < 4; q++) {
                    int row = 4 * rg + q;
                    if (row < M) {
                        float a = 0.f;
#pragma unroll
                        for (int d = 0; d < K; d++) a = fmaf(g[d], r[q + d], a);
                        sMEAN[row * MS + c] = a;
                    }
                }
            }
        }
        // s2 at center pixels only (exact 256-thread map: col tx, rows 4*ty..4*ty+3)
        float s2q[4];
        {
            float r[K + 3];
#pragma unroll
            for (int d = 0; d < K + 3; d++)
                r[d] = sT2[(R + 4 * ty + d) * MS + R + tx];
#pragma unroll
            for (int q = 0; q < 4; q++) {
                float b = 0.f;
#pragma unroll
                for (int d = 0; d < K; d++) b = fmaf(g[d], r[q + d], b);
                s2q[q] = b;
            }
        }
        __syncthreads();

        // ---- P3: xc^3, xc^4 on the M x M grid (xc == 0 outside image) ----
        for (int idx = tid; idx < M * M; idx += 256) {
            int m = idx / M, i = idx - m * M;
            int gy = gy0 - R + m, gx = gx0 - R + i;
            float c = 0.f;
            if ((unsigned)gy < (unsigned)IMGH && (unsigned)gx < (unsigned)IMGW)
                c = sX[(m + R) * XS + i + R] - sMEAN[m * MS + i];
            float c3 = c * c * c;
            sC3[m * MS + i] = c3;
            sC4[m * MS + i] = c3 * c;
        }
        float meanq[4];
#pragma unroll
        for (int q = 0; q < 4; q++)
            meanq[q] = sMEAN[(4 * ty + q + R) * MS + tx + R];
        __syncthreads();

        // ---- P4: horizontal conv of xc^3/xc^4 (M rows x 32 center cols), 4 cols/thread ----
#pragma unroll
        for (int it = 0; it < (P4_ITEMS + 255) / 256; it++) {
            int item = tid + it * 256;
            if (item < P4_ITEMS) {
                int m = item >> 3, g4 = item & 7;
                float x3[4 * NV], x4[4 * NV];
                const float4* s3 = reinterpret_cast<const float4*>(&sC3[m * MS + 4 * g4]);
                const float4* s4 = reinterpret_cast<const float4*>(&sC4[m * MS + 4 * g4]);
#pragma unroll
                for (int w = 0; w < NV; w++) {
                    float4 v = s3[w];
                    x3[4 * w + 0] = v.x; x3[4 * w + 1] = v.y;
                    x3[4 * w + 2] = v.z; x3[4 * w + 3] = v.w;
                    float4 u = s4[w];
                    x4[4 * w + 0] = u.x; x4[4 * w + 1] = u.y;
                    x4[4 * w + 2] = u.z; x4[4 * w + 3] = u.w;
                }
                float a[4] = {0.f, 0.f, 0.f, 0.f};
                float b[4] = {0.f, 0.f, 0.f, 0.f};
#pragma unroll
                for (int d = 0; d < K; d++)
#pragma unroll
                    for (int q = 0; q < 4; q++) {
                        a[q] = fmaf(g[d], x3[q + d], a[q]);
                        b[q] = fmaf(g[d], x4[q + d], b[q]);
                    }
                *reinterpret_cast<float4*>(&sT1[m * MS + 4 * g4]) =
                    make_float4(a[0], a[1], a[2], a[3]);
                *reinterpret_cast<float4*>(&sT2[m * MS + 4 * g4]) =
                    make_float4(b[0], b[1], b[2], b[3]);
            }
        }
        __syncthreads();

        // ---- P5: vertical conv -> m3, m4 at center; features + loss ----
        {
            float r3[K + 3], r4[K + 3];
#pragma unroll
            for (int d = 0; d < K + 3; d++) {
                r3[d] = sT1[(4 * ty + d) * MS + tx];
                r4[d] = sT2[(4 * ty + d) * MS + tx];
            }
#pragma unroll
            for (int q = 0; q < 4; q++) {
                float m3 = 0.f, m4 = 0.f;
#pragma unroll
                for (int d = 0; d < K; d++) {
                    m3 = fmaf(g[d], r3[q + d], m3);
                    m4 = fmaf(g[d], r4[q + d], m4);
                }
                float mean = meanq[q];
                float var  = fmaxf(s2q[q] - mean * mean, FEPS);
                float sd   = sqrtf(var);
                float skew = m3 / (sd * sd * sd + FEPS);
                float kurt = m4 / (var * var + FEPS);
                if (which == 0) {
                    fpm[q] = mean; fpv[q] = var; fps[q] = skew; fpk[q] = kurt;
                } else {
                    acc += 1.0   * (double)fabsf(fpm[q] - mean);
                    acc += 1.0   * (double)fabsf(fpv[q] - var);
                    acc += 0.5   * (double)fabsf(fps[q] - skew);
                    acc += 0.001 * (double)fabsf(fpk[q] - kurt);
                }
            }
        }
        __syncthreads();   // before smem reuse by next input
    }

    // ---- block reduce in double ----
#pragma unroll
    for (int o = 16; o > 0; o >>= 1)
        acc += __shfl_down_sync(0xffffffffu, acc, o);
    if (tx == 0) sRed[ty] = acc;
    __syncthreads();
    if (tid < 8) {
        double a = sRed[tid];
#pragma unroll
        for (int o = 4; o > 0; o >>= 1)
            a += __shfl_down_sync(0xffu, a, o);
        if (tid == 0) {
            int blin = (blockIdx.z * gridDim.y + blockIdx.y) * gridDim.x + blockIdx.x;
            g_partial[winIdx * TILES + blin] = a;
        }
    }
}

__global__ __launch_bounds__(1024)
void finalize_kernel(float* __restrict__ out)
{
    __shared__ double sRed[32];
    double a = 0.0;
    const double2* p2 = reinterpret_cast<const double2*>(g_partial);
#pragma unroll 4
    for (int i = threadIdx.x; i < (3 * TILES) / 2; i += 1024) {
        double2 v = p2[i];
        a += v.x + v.y;
    }
#pragma unroll
    for (int o = 16; o > 0; o >>= 1)
        a += __shfl_down_sync(0xffffffffu, a, o);
    if ((threadIdx.x & 31) == 0) sRed[threadIdx.x >> 5] = a;
    __syncthreads();
    if (threadIdx.x < 32) {
        double v = sRed[threadIdx.x];
#pragma unroll
        for (int o = 16; o > 0; o >>= 1)
            v += __shfl_down_sync(0xffffffffu, v, o);
        if (threadIdx.x == 0) {
            const double npix = (double)16 * 3 * 512 * 512;
            out[0] = (float)(v / (npix * 12.0));
        }
    }
}

extern "C" void kernel_launch(void* const* d_in, const int* in_sizes, int n_in,
                              void* d_out, int out_size)
{
    const float* pred   = (const float*)d_in[0];
    const float* target = (const float*)d_in[1];

    dim3 grid(IMGW / T, IMGH / T, NIMG);   // 16 x 16 x 48 tiles
    statloss_kernel<3><<<grid, 256>>>(pred, target, 0);
    statloss_kernel<5><<<grid, 256>>>(pred, target, 1);
    statloss_kernel<7><<<grid, 256>>>(pred, target, 2);
    finalize_kernel<<<1, 1024>>>((float*)d_out);
}

// round 12
// speedup vs baseline: 1.3634x; 1.3634x over previous
#include <cuda_runtime.h>
#include <math.h>

static constexpr int T    = 32;
static constexpr int IMGW = 512, IMGH = 512, NIMG = 48;   // 16*3 images of 512x512
static constexpr int TILES = (IMGW / T) * (IMGH / T) * NIMG;  // 12288
static constexpr float FEPS = 1e-8f;

// per-(window,block) partial sums; every slot written every launch -> deterministic
__device__ __align__(16) double g_partial[3 * TILES];
__device__ unsigned int g_ticket = 0;

template <int K> struct Cfg {
    static constexpr int R  = K / 2;
    static constexpr int H  = T + 4 * R;   // x tile extent (halo 2R)
    static constexpr int M  = T + 2 * R;   // mean/xc extent (halo R)
    static constexpr int XS = H + 1;
    static constexpr int MS = M + 1;
    static constexpr int TS = T + 1;
    static constexpr int FLOATS =
        2 * H * XS + 2 * H * MS + 2 * M * TS + 2 * M * MS;
    static constexpr int BYTES = FLOATS * 4;
};

template <int K>
__global__ __launch_bounds__(256, 4)
void statloss_kernel(const float* __restrict__ pred,
                     const float* __restrict__ target,
                     int winIdx, float* __restrict__ out)
{
    constexpr int R  = Cfg<K>::R;
    constexpr int H  = Cfg<K>::H;
    constexpr int M  = Cfg<K>::M;
    constexpr int XS = Cfg<K>::XS;
    constexpr int MS = Cfg<K>::MS;
    constexpr int TS = Cfg<K>::TS;

    extern __shared__ float smem[];
    float* sXa  = smem;                  // H x XS : x tile (a), live -> P3
    float* sXb  = sXa  + H * XS;         // H x XS : x tile (b)
    float* sT1a = sXb  + H * XS;         // H x MS : h(x) (P1->P2) then c (P3->P4)
    float* sT1b = sT1a + H * MS;
    float* sT2a = sT1b + H * MS;         // M x TS : h(x^2) center (P1->P2) then h3 (P4->P5)
    float* sT2b = sT2a + M * TS;
    float* sMa  = sT2b + M * TS;         // M x MS : mean (P2->P3) then h4 (P4->P5)
    float* sMb  = sMa  + M * MS;
    __shared__ double sRed[8];
    __shared__ int sLast;

    const int tid = threadIdx.x;
    const int tx  = tid & 31;
    const int ty  = tid >> 5;            // center rows ty + {0,8,16,24}

    // normalized 1-D gaussian (separable; outer product already sums to 1)
    float g[K];
    {
        const float sigma = (float)K / 6.0f;
        float s = 0.f;
#pragma unroll
        for (int i = 0; i < K; i++) {
            float c = (float)(i - K / 2);
            g[i] = expf(-c * c / (2.0f * sigma * sigma));
            s += g[i];
        }
#pragma unroll
        for (int i = 0; i < K; i++) g[i] /= s;
    }

    const int gx0 = blockIdx.x * T;
    const int gy0 = blockIdx.y * T;
    const size_t base = (size_t)blockIdx.z * IMGH * IMGW;
    const float* pa = pred + base;
    const float* pb = target + base;

    // ---- load both x tiles with 2R halo (zero pad outside image) ----
    for (int idx = tid; idx < H * H; idx += 256) {
        int j = idx / H, i = idx - j * H;
        int gy = gy0 - 2 * R + j, gx = gx0 - 2 * R + i;
        float va = 0.f, vb = 0.f;
        if ((unsigned)gy < (unsigned)IMGH && (unsigned)gx < (unsigned)IMGW) {
            size_t o = (size_t)gy * IMGW + gx;
            va = pa[o];
            vb = pb[o];
        }
        sXa[j * XS + i] = va;
        sXb[j * XS + i] = vb;
    }
    __syncthreads();

    // ---- P1: horizontal conv; h(x) on H x M; h(x^2) only at center cols ----
    for (int idx = tid; idx < H * M; idx += 256) {
        int j = idx / M, i = idx - j * M;
        float a1 = 0.f, a2 = 0.f, b1 = 0.f, b2 = 0.f;
#pragma unroll
        for (int d = 0; d < K; d++) {
            float va = sXa[j * XS + i + d];
            float vb = sXb[j * XS + i + d];
            a1 = fmaf(g[d], va, a1);
            a2 = fmaf(g[d] * va, va, a2);
            b1 = fmaf(g[d], vb, b1);
            b2 = fmaf(g[d] * vb, vb, b2);
        }
        sT1a[j * MS + i] = a1;
        sT1b[j * MS + i] = b1;
        if (j >= R && j < R + M && i >= R && i < R + T) {
            sT2a[(j - R) * TS + (i - R)] = a2;
            sT2b[(j - R) * TS + (i - R)] = b2;
        }
    }
    __syncthreads();

    // ---- P2: vertical conv -> MEAN (M x M) both; s2 at center to regs ----
    for (int idx = tid; idx < M * M; idx += 256) {
        int m = idx / M, i = idx - m * M;
        float a = 0.f, b = 0.f;
#pragma unroll
        for (int d = 0; d < K; d++) {
            a = fmaf(g[d], sT1a[(m + d) * MS + i], a);
            b = fmaf(g[d], sT1b[(m + d) * MS + i], b);
        }
        sMa[m * MS + i] = a;
        sMb[m * MS + i] = b;
    }
    float s2qa[4], s2qb[4];
#pragma unroll
    for (int q = 0; q < 4; q++) {
        int yy = ty + 8 * q;
        float a = 0.f, b = 0.f;
#pragma unroll
        for (int d = 0; d < K; d++) {
            a = fmaf(g[d], sT2a[(yy + d) * TS + tx], a);
            b = fmaf(g[d], sT2b[(yy + d) * TS + tx], b);
        }
        s2qa[q] = a;
        s2qb[q] = b;
    }
    __syncthreads();

    // ---- P3: c = x - mean on M x M (c==0 outside image) -> sT1*; cache mean center ----
    for (int idx = tid; idx < M * M; idx += 256) {
        int m = idx / M, i = idx - m * M;
        int gy = gy0 - R + m, gx = gx0 - R + i;
        bool in = (unsigned)gy < (unsigned)IMGH && (unsigned)gx < (unsigned)IMGW;
        float ca = 0.f, cb = 0.f;
        if (in) {
            ca = sXa[(m + R) * XS + i + R] - sMa[m * MS + i];
            cb = sXb[(m + R) * XS + i + R] - sMb[m * MS + i];
        }
        sT1a[m * MS + i] = ca;
        sT1b[m * MS + i] = cb;
    }
    float mqa[4], mqb[4];
#pragma unroll
    for (int q = 0; q < 4; q++) {
        int yy = ty + 8 * q + R;
        mqa[q] = sMa[yy * MS + tx + R];
        mqb[q] = sMb[yy * MS + tx + R];
    }
    __syncthreads();

    // ---- P4: horizontal conv of c^3/c^4 (computed from c on the fly) ----
    //      h3 -> sT2* (M x TS), h4 -> sM* (M x MS, cols [0,T))
    for (int idx = tid; idx < M * T; idx += 256) {
        int m = idx >> 5, t = idx & 31;
        float a3 = 0.f, a4 = 0.f, b3 = 0.f, b4 = 0.f;
#pragma unroll
        for (int d = 0; d < K; d++) {
            float ca = sT1a[m * MS + t + d];
            float cb = sT1b[m * MS + t + d];
            float ca3 = ca * ca * ca;
            float cb3 = cb * cb * cb;
            a3 = fmaf(g[d], ca3, a3);
            a4 = fmaf(g[d] * ca3, ca, a4);
            b3 = fmaf(g[d], cb3, b3);
            b4 = fmaf(g[d] * cb3, cb, b4);
        }
        sT2a[m * TS + t] = a3;
        sMa[m * MS + t]  = a4;
        sT2b[m * TS + t] = b3;
        sMb[m * MS + t]  = b4;
    }
    __syncthreads();

    // ---- P5: vertical conv -> m3, m4; features + loss for both inputs ----
    double acc = 0.0;
#pragma unroll
    for (int q = 0; q < 4; q++) {
        int yy = ty + 8 * q;
        float m3a = 0.f, m4a = 0.f, m3b = 0.f, m4b = 0.f;
#pragma unroll
        for (int d = 0; d < K; d++) {
            m3a = fmaf(g[d], sT2a[(yy + d) * TS + tx], m3a);
            m4a = fmaf(g[d], sMa[(yy + d) * MS + tx],  m4a);
            m3b = fmaf(g[d], sT2b[(yy + d) * TS + tx], m3b);
            m4b = fmaf(g[d], sMb[(yy + d) * MS + tx],  m4b);
        }
        float va = fmaxf(s2qa[q] - mqa[q] * mqa[q], FEPS);
        float vb = fmaxf(s2qb[q] - mqb[q] * mqb[q], FEPS);
        float sda = sqrtf(va), sdb = sqrtf(vb);
        float ska = m3a / (sda * sda * sda + FEPS);
        float skb = m3b / (sdb * sdb * sdb + FEPS);
        float kua = m4a / (va * va + FEPS);
        float kub = m4b / (vb * vb + FEPS);
        acc += 1.0   * (double)fabsf(mqa[q] - mqb[q]);
        acc += 1.0   * (double)fabsf(va - vb);
        acc += 0.5   * (double)fabsf(ska - skb);
        acc += 0.001 * (double)fabsf(kua - kub);
    }

    // ---- block reduce in double, write partial ----
#pragma unroll
    for (int o = 16; o > 0; o >>= 1)
        acc += __shfl_down_sync(0xffffffffu, acc, o);
    if (tx == 0) sRed[ty] = acc;
    __syncthreads();
    if (tid < 8) {
        double a = sRed[tid];
#pragma unroll
        for (int o = 4; o > 0; o >>= 1)
            a += __shfl_down_sync(0xffu, a, o);
        if (tid == 0) {
            int blin = (blockIdx.z * gridDim.y + blockIdx.y) * gridDim.x + blockIdx.x;
            g_partial[winIdx * TILES + blin] = a;
        }
    }

    // ---- last block of the whole 3-kernel sequence does the final sum ----
    if (tid == 0) {
        __threadfence();
        unsigned t = atomicAdd(&g_ticket, 1u);
        sLast = (t == 3u * TILES - 1u) ? 1 : 0;
    }
    __syncthreads();
    if (sLast) {
        __threadfence();
        double a = 0.0;
        const double2* p2 = reinterpret_cast<const double2*>(g_partial);
        for (int i = tid; i < (3 * TILES) / 2; i += 256) {
            double2 v = __ldcg(&p2[i]);
            a += v.x + v.y;
        }
#pragma unroll
        for (int o = 16; o > 0; o >>= 1)
            a += __shfl_down_sync(0xffffffffu, a, o);
        if (tx == 0) sRed[ty] = a;
        __syncthreads();
        if (tid < 8) {
            double v = sRed[tid];
#pragma unroll
            for (int o = 4; o > 0; o >>= 1)
                v += __shfl_down_sync(0xffu, v, o);
            if (tid == 0) {
                const double npix = (double)16 * 3 * 512 * 512;
                out[0] = (float)(v / (npix * 12.0));
                g_ticket = 0;   // reset for next (deterministic) run
            }
        }
    }
}

extern "C" void kernel_launch(void* const* d_in, const int* in_sizes, int n_in,
                              void* d_out, int out_size)
{
    const float* pred   = (const float*)d_in[0];
    const float* target = (const float*)d_in[1];
    float* out = (float*)d_out;

    // opt-in for >48KB dynamic smem (host-side attribute; not an allocation)
    cudaFuncSetAttribute(statloss_kernel<3>,
                         cudaFuncAttributeMaxDynamicSharedMemorySize, Cfg<3>::BYTES);
    cudaFuncSetAttribute(statloss_kernel<5>,
                         cudaFuncAttributeMaxDynamicSharedMemorySize, Cfg<5>::BYTES);
    cudaFuncSetAttribute(statloss_kernel<7>,
                         cudaFuncAttributeMaxDynamicSharedMemorySize, Cfg<7>::BYTES);

    dim3 grid(IMGW / T, IMGH / T, NIMG);   // 16 x 16 x 48 tiles
    statloss_kernel<3><<<grid, 256, Cfg<3>::BYTES>>>(pred, target, 0, out);
    statloss_kernel<5><<<grid, 256, Cfg<5>::BYTES>>>(pred, target, 1, out);
    statloss_kernel<7><<<grid, 256, Cfg<7>::BYTES>>>(pred, target, 2, out);
}

// round 16
// speedup vs baseline: 1.4358x; 1.0531x over previous
#include <cuda_runtime.h>
#include <math.h>

static constexpr int T    = 32;
static constexpr int IMGW = 512, IMGH = 512, NIMG = 48;   // 16*3 images of 512x512
static constexpr int TILES = (IMGW / T) * (IMGH / T) * NIMG;  // 12288
static constexpr float FEPS = 1e-8f;

// per-(window,block) partial sums; every slot written every launch -> deterministic
__device__ __align__(16) double g_partial[3 * TILES];
__device__ unsigned int g_ticket = 0;

template <int K> struct Cfg {
    static constexpr int R  = K / 2;
    static constexpr int H  = T + 4 * R;   // x tile extent (halo 2R), even
    static constexpr int M  = T + 2 * R;   // mean/c extent (halo R), even
    static constexpr int XS = H + 2;       // even strides -> float2 aligned
    static constexpr int MS = M + 2;
    static constexpr int FLOATS = 2 * H * XS + 2 * H * MS + 4 * M * MS;
    static constexpr int BYTES  = FLOATS * 4;
};

template <int K>
__global__ __launch_bounds__(256, (K == 3) ? 5 : 4)
void statloss_kernel(const float* __restrict__ pred,
                     const float* __restrict__ target,
                     int winIdx, float* __restrict__ out)
{
    constexpr int R  = Cfg<K>::R;
    constexpr int H  = Cfg<K>::H;
    constexpr int M  = Cfg<K>::M;
    constexpr int XS = Cfg<K>::XS;
    constexpr int MS = Cfg<K>::MS;
    constexpr int HP = H / 2;
    constexpr int MP = M / 2;

    extern __shared__ float smem[];
    float* sXa  = smem;                  // H x XS : x tile (a)
    float* sXb  = sXa  + H * XS;
    float* sT1a = sXb  + H * XS;         // H x MS : h(x) (P1->P2), then c (P3->P4)
    float* sT1b = sT1a + H * MS;
    float* sT2a = sT1b + H * MS;         // M x MS : h(x^2) (P1->P2), then h3 (P4->P5)
    float* sT2b = sT2a + M * MS;
    float* sMa  = sT2b + M * MS;         // M x MS : mean (P2->P3), then h4 (P4->P5)
    float* sMb  = sMa  + M * MS;
    __shared__ double sRed[8];
    __shared__ int sLast;

    const int tid = threadIdx.x;
    const int c2  = 2 * (tid & 15);      // owned center col pair: c2, c2+1
    const int r0  = tid >> 4;            // owned center rows: r0, r0+16

    // normalized 1-D gaussian (separable; outer product already sums to 1)
    float g[K];
    {
        const float sigma = (float)K / 6.0f;
        float s = 0.f;
#pragma unroll
        for (int i = 0; i < K; i++) {
            float c = (float)(i - K / 2);
            g[i] = expf(-c * c / (2.0f * sigma * sigma));
            s += g[i];
        }
#pragma unroll
        for (int i = 0; i < K; i++) g[i] /= s;
    }

    const int gx0 = blockIdx.x * T;
    const int gy0 = blockIdx.y * T;
    const size_t base = (size_t)blockIdx.z * IMGH * IMGW;
    const float* pa = pred + base;
    const float* pb = target + base;

    // ---- load both x tiles with 2R halo, float2 pairs (zero pad outside) ----
    for (int idx = tid; idx < H * HP; idx += 256) {
        int j = idx / HP, pi = idx - j * HP;
        int i0 = 2 * pi;
        int gy = gy0 - 2 * R + j, gx = gx0 - 2 * R + i0;   // gx even
        float2 va = make_float2(0.f, 0.f), vb = make_float2(0.f, 0.f);
        if ((unsigned)gy < (unsigned)IMGH && (unsigned)gx < (unsigned)IMGW) {
            size_t o = (size_t)gy * IMGW + gx;
            va = *reinterpret_cast<const float2*>(pa + o);
            vb = *reinterpret_cast<const float2*>(pb + o);
        }
        *reinterpret_cast<float2*>(&sXa[j * XS + i0]) = va;
        *reinterpret_cast<float2*>(&sXb[j * XS + i0]) = vb;
    }
    __syncthreads();

    // ---- P1: horizontal conv of x and x^2, 2 cols/item, inputs sequential ----
    for (int idx = tid; idx < H * MP; idx += 256) {
        int j = idx / MP, pi = idx - j * MP;
        int i0 = 2 * pi;
        bool ctr = (j >= R) && (j < R + M);
#pragma unroll
        for (int which = 0; which < 2; which++) {
            const float* sX  = which ? sXb : sXa;
            float* d1 = which ? sT1b : sT1a;
            float* d2 = which ? sT2b : sT2a;
            float xv[2 * R + 2], xs[2 * R + 2];
#pragma unroll
            for (int w = 0; w <= R; w++) {
                float2 v = *reinterpret_cast<const float2*>(&sX[j * XS + i0 + 2 * w]);
                xv[2 * w] = v.x; xv[2 * w + 1] = v.y;
            }
#pragma unroll
            for (int t = 0; t < 2 * R + 2; t++) xs[t] = xv[t] * xv[t];
            float a10 = 0.f, a11 = 0.f, a20 = 0.f, a21 = 0.f;
#pragma unroll
            for (int d = 0; d < K; d++) {
                a10 = fmaf(g[d], xv[d],     a10);
                a11 = fmaf(g[d], xv[d + 1], a11);
                a20 = fmaf(g[d], xs[d],     a20);
                a21 = fmaf(g[d], xs[d + 1], a21);
            }
            *reinterpret_cast<float2*>(&d1[j * MS + i0]) = make_float2(a10, a11);
            if (ctr)
                *reinterpret_cast<float2*>(&d2[(j - R) * MS + i0]) = make_float2(a20, a21);
        }
    }
    __syncthreads();

    // ---- P2: vertical conv -> MEAN (M x M), float2; s2 at owned pixels ----
    for (int idx = tid; idx < M * MP; idx += 256) {
        int m = idx / MP, pi = idx - m * MP;
        int i0 = 2 * pi;
        float2 am = make_float2(0.f, 0.f), bm = make_float2(0.f, 0.f);
#pragma unroll
        for (int d = 0; d < K; d++) {
            float2 va = *reinterpret_cast<const float2*>(&sT1a[(m + d) * MS + i0]);
            float2 vb = *reinterpret_cast<const float2*>(&sT1b[(m + d) * MS + i0]);
            am.x = fmaf(g[d], va.x, am.x); am.y = fmaf(g[d], va.y, am.y);
            bm.x = fmaf(g[d], vb.x, bm.x); bm.y = fmaf(g[d], vb.y, bm.y);
        }
        *reinterpret_cast<float2*>(&sMa[m * MS + i0]) = am;
        *reinterpret_cast<float2*>(&sMb[m * MS + i0]) = bm;
    }
    float s2a[2][2], s2b[2][2];
#pragma unroll
    for (int ri = 0; ri < 2; ri++) {
        int rr = r0 + 16 * ri;
#pragma unroll
        for (int jj = 0; jj < 2; jj++) {
            int cc = c2 + jj + R;
            float a = 0.f, b = 0.f;
#pragma unroll
            for (int d = 0; d < K; d++) {
                a = fmaf(g[d], sT2a[(rr + d) * MS + cc], a);
                b = fmaf(g[d], sT2b[(rr + d) * MS + cc], b);
            }
            s2a[ri][jj] = a; s2b[ri][jj] = b;
        }
    }
    __syncthreads();

    // ---- P3: c = x - mean on M x M (c==0 outside image) -> sT1*; cache mean ----
    for (int idx = tid; idx < M * MP; idx += 256) {
        int m = idx / MP, pi = idx - m * MP;
        int i0 = 2 * pi;
        int gy = gy0 - R + m;
        int gxb = gx0 - R + i0;
        bool iny = (unsigned)gy < (unsigned)IMGH;
        float2 ma = *reinterpret_cast<const float2*>(&sMa[m * MS + i0]);
        float2 mb = *reinterpret_cast<const float2*>(&sMb[m * MS + i0]);
        float ca0 = 0.f, ca1 = 0.f, cb0 = 0.f, cb1 = 0.f;
        if (iny && (unsigned)gxb < (unsigned)IMGW) {
            ca0 = sXa[(m + R) * XS + i0 + R] - ma.x;
            cb0 = sXb[(m + R) * XS + i0 + R] - mb.x;
        }
        if (iny && (unsigned)(gxb + 1) < (unsigned)IMGW) {
            ca1 = sXa[(m + R) * XS + i0 + R + 1] - ma.y;
            cb1 = sXb[(m + R) * XS + i0 + R + 1] - mb.y;
        }
        *reinterpret_cast<float2*>(&sT1a[m * MS + i0]) = make_float2(ca0, ca1);
        *reinterpret_cast<float2*>(&sT1b[m * MS + i0]) = make_float2(cb0, cb1);
    }
    float mqa_[2][2], mqb_[2][2];
#pragma unroll
    for (int ri = 0; ri < 2; ri++) {
        int rr = r0 + 16 * ri + R;
#pragma unroll
        for (int jj = 0; jj < 2; jj++) {
            mqa_[ri][jj] = sMa[rr * MS + c2 + jj + R];
            mqb_[ri][jj] = sMb[rr * MS + c2 + jj + R];
        }
    }
    __syncthreads();

    // ---- P4: horizontal conv of c^3/c^4, 2 cols/item, inputs sequential ----
    for (int idx = tid; idx < M * (T / 2); idx += 256) {
        int m = idx >> 4, pt = idx & 15;
        int t0 = 2 * pt;
#pragma unroll
        for (int which = 0; which < 2; which++) {
            const float* sc = which ? sT1b : sT1a;
            float* d3 = which ? sT2b : sT2a;
            float* d4 = which ? sMb  : sMa;
            float c3[2 * R + 2], c4[2 * R + 2];
#pragma unroll
            for (int w = 0; w <= R; w++) {
                float2 v = *reinterpret_cast<const float2*>(&sc[m * MS + t0 + 2 * w]);
                float q0 = v.x * v.x, q1 = v.y * v.y;
                c3[2 * w]     = q0 * v.x;  c4[2 * w]     = q0 * q0;
                c3[2 * w + 1] = q1 * v.y;  c4[2 * w + 1] = q1 * q1;
            }
            float h30 = 0.f, h31 = 0.f, h40 = 0.f, h41 = 0.f;
#pragma unroll
            for (int d = 0; d < K; d++) {
                h30 = fmaf(g[d], c3[d],     h30);
                h31 = fmaf(g[d], c3[d + 1], h31);
                h40 = fmaf(g[d], c4[d],     h40);
                h41 = fmaf(g[d], c4[d + 1], h41);
            }
            *reinterpret_cast<float2*>(&d3[m * MS + t0]) = make_float2(h30, h31);
            *reinterpret_cast<float2*>(&d4[m * MS + t0]) = make_float2(h40, h41);
        }
    }
    __syncthreads();

    // ---- P5: vertical conv -> m3, m4 (float2); features + loss ----
    double acc = 0.0;
#pragma unroll
    for (int ri = 0; ri < 2; ri++) {
        int rr = r0 + 16 * ri;
        float2 m3a = make_float2(0.f, 0.f), m4a = make_float2(0.f, 0.f);
        float2 m3b = make_float2(0.f, 0.f), m4b = make_float2(0.f, 0.f);
#pragma unroll
        for (int d = 0; d < K; d++) {
            float2 v;
            v = *reinterpret_cast<const float2*>(&sT2a[(rr + d) * MS + c2]);
            m3a.x = fmaf(g[d], v.x, m3a.x); m3a.y = fmaf(g[d], v.y, m3a.y);
            v = *reinterpret_cast<const float2*>(&sMa[(rr + d) * MS + c2]);
            m4a.x = fmaf(g[d], v.x, m4a.x); m4a.y = fmaf(g[d], v.y, m4a.y);
            v = *reinterpret_cast<const float2*>(&sT2b[(rr + d) * MS + c2]);
            m3b.x = fmaf(g[d], v.x, m3b.x); m3b.y = fmaf(g[d], v.y, m3b.y);
            v = *reinterpret_cast<const float2*>(&sMb[(rr + d) * MS + c2]);
            m4b.x = fmaf(g[d], v.x, m4b.x); m4b.y = fmaf(g[d], v.y, m4b.y);
        }
#pragma unroll
        for (int jj = 0; jj < 2; jj++) {
            float m3av = jj ? m3a.y : m3a.x, m4av = jj ? m4a.y : m4a.x;
            float m3bv = jj ? m3b.y : m3b.x, m4bv = jj ? m4b.y : m4b.x;
            float mav = mqa_[ri][jj], mbv = mqb_[ri][jj];
            float va = fmaxf(s2a[ri][jj] - mav * mav, FEPS);
            float vb = fmaxf(s2b[ri][jj] - mbv * mbv, FEPS);
            float sda = sqrtf(va), sdb = sqrtf(vb);
            float ska = m3av / (sda * sda * sda + FEPS);
            float skb = m3bv / (sdb * sdb * sdb + FEPS);
            float kua = m4av / (va * va + FEPS);
            float kub = m4bv / (vb * vb + FEPS);
            acc += 1.0   * (double)fabsf(mav - mbv);
            acc += 1.0   * (double)fabsf(va - vb);
            acc += 0.5   * (double)fabsf(ska - skb);
            acc += 0.001 * (double)fabsf(kua - kub);
        }
    }

    // ---- block reduce in double, write partial ----
#pragma unroll
    for (int o = 16; o > 0; o >>= 1)
        acc += __shfl_down_sync(0xffffffffu, acc, o);
    if ((tid & 31) == 0) sRed[tid >> 5] = acc;
    __syncthreads();
    if (tid < 8) {
        double a = sRed[tid];
#pragma unroll
        for (int o = 4; o > 0; o >>= 1)
            a += __shfl_down_sync(0xffu, a, o);
        if (tid == 0) {
            int blin = (blockIdx.z * gridDim.y + blockIdx.y) * gridDim.x + blockIdx.x;
            g_partial[winIdx * TILES + blin] = a;
        }
    }

    // ---- last block of the whole 3-kernel sequence does the final sum ----
    if (tid == 0) {
        __threadfence();
        unsigned t = atomicAdd(&g_ticket, 1u);
        sLast = (t == 3u * TILES - 1u) ? 1 : 0;
    }
    __syncthreads();
    if (sLast) {
        __threadfence();
        double a = 0.0;
        const double2* p2 = reinterpret_cast<const double2*>(g_partial);
        for (int i = tid; i < (3 * TILES) / 2; i += 256) {
            double2 v = __ldcg(&p2[i]);
            a += v.x + v.y;
        }
#pragma unroll
        for (int o = 16; o > 0; o >>= 1)
            a += __shfl_down_sync(0xffffffffu, a, o);
        if ((tid & 31) == 0) sRed[tid >> 5] = a;
        __syncthreads();
        if (tid < 8) {
            double v = sRed[tid];
#pragma unroll
            for (int o = 4; o > 0; o >>= 1)
                v += __shfl_down_sync(0xffu, v, o);
            if (tid == 0) {
                const double npix = (double)16 * 3 * 512 * 512;
                out[0] = (float)(v / (npix * 12.0));
                g_ticket = 0;   // reset for next (deterministic) run
            }
        }
    }
}

extern "C" void kernel_launch(void* const* d_in, const int* in_sizes, int n_in,
                              void* d_out, int out_size)
{
    const float* pred   = (const float*)d_in[0];
    const float* target = (const float*)d_in[1];
    float* out = (float*)d_out;

    // opt-in for >48KB dynamic smem (host-side attribute; not an allocation)
    cudaFuncSetAttribute(statloss_kernel<3>,
                         cudaFuncAttributeMaxDynamicSharedMemorySize, Cfg<3>::BYTES);
    cudaFuncSetAttribute(statloss_kernel<5>,
                         cudaFuncAttributeMaxDynamicSharedMemorySize, Cfg<5>::BYTES);
    cudaFuncSetAttribute(statloss_kernel<7>,
                         cudaFuncAttributeMaxDynamicSharedMemorySize, Cfg<7>::BYTES);

    dim3 grid(IMGW / T, IMGH / T, NIMG);   // 16 x 16 x 48 tiles
    statloss_kernel<3><<<grid, 256, Cfg<3>::BYTES>>>(pred, target, 0, out);
    statloss_kernel<5><<<grid, 256, Cfg<5>::BYTES>>>(pred, target, 1, out);
    statloss_kernel<7><<<grid, 256, Cfg<7>::BYTES>>>(pred, target, 2, out);
}